// round 13
// baseline (speedup 1.0000x reference)
#include <cuda_runtime.h>
#include <cuda_bf16.h>
#include <cstdint>
#include <cstring>

#define DD 1024
#define MM 256
#define BB 2048
#define NCH 8          // chunks per tile, 128 d each
#define NT2 256        // tiles: 32b x 64m x 1024d  (64 bT x 4 mT)
#define NCTA 148
#define XSTG 512       // uint4 per x stage (32 rows x 16)
#define CSTG 2112      // uint4 per c stage (64 rows x 33, odd stride)

// Device scratch (no allocations allowed)
__device__ __align__(16) uint32_t g_cb[MM * DD];          // per d-pair: {c1 bf16x2, c0 bf16x2}
__device__ __align__(16) uint32_t g_xb[BB * (DD / 2)];    // x as bf16x2 pairs
__device__ __align__(16) float g_logw[MM];
__device__ __align__(16) float g_comp[BB * MM];           // sum over d of log2(2*lik)
__device__ int g_ctr;

__device__ __forceinline__ __nv_bfloat162 asbf2(uint32_t u) {
    __nv_bfloat162 r; memcpy(&r, &u, 4); return r;
}
__device__ __forceinline__ uint32_t asu32(__nv_bfloat162 b) {
    uint32_t u; memcpy(&u, &b, 4); return u;
}
__device__ __forceinline__ void cp16(uint32_t dst, const void* src) {
    asm volatile("cp.async.ca.shared.global [%0], [%1], 16;" :: "r"(dst), "l"(src));
}
__device__ __forceinline__ uint32_t packbf(float a, float b) {
    return asu32(__floats2bfloat162_rn(a, b));
}

// ---------------------------------------------------------------------------
// Fused prep (R8): blocks [0,256) x->bf16 (MLP8 loads, STG.128 stores);
// [256,320) P->coefs (MLP8); block 320: logw + tile-counter reset.
// ---------------------------------------------------------------------------
__global__ void prep_kernel(const float* __restrict__ x,
                            const float* __restrict__ P,
                            const float* __restrict__ W) {
    int bk = blockIdx.x, t = threadIdx.x;
    if (bk < 256) {
        const float4* src = reinterpret_cast<const float4*>(x) + bk * 2048;
        uint4* dst = reinterpret_cast<uint4*>(g_xb) + bk * 1024;
        float4 v[4][2];
#pragma unroll
        for (int k = 0; k < 4; k++) {
            v[k][0] = src[k * 512 + t * 2];
            v[k][1] = src[k * 512 + t * 2 + 1];
        }
#pragma unroll
        for (int k = 0; k < 4; k++) {
            uint4 w;
            w.x = packbf(v[k][0].x, v[k][0].y);
            w.y = packbf(v[k][0].z, v[k][0].w);
            w.z = packbf(v[k][1].x, v[k][1].y);
            w.w = packbf(v[k][1].z, v[k][1].w);
            dst[k * 256 + t] = w;
        }
    } else if (bk < 320) {
        int b2 = bk - 256;
        const float2* src = reinterpret_cast<const float2*>(P) + b2 * 2048 + t;
        uint2* dst = reinterpret_cast<uint2*>(g_cb) + b2 * 2048 + t;
        float2 v[8];
#pragma unroll
        for (int k = 0; k < 8; k++) v[k] = src[k * 256];
#pragma unroll
        for (int k = 0; k < 8; k++) {
            float c0a = 2.0f / (1.0f + __expf(v[k].x));   // 2*(1-p)
            float c0b = 2.0f / (1.0f + __expf(v[k].y));
            float c1a = 2.0f - 2.0f * c0a;                // 2*(2p-1)
            float c1b = 2.0f - 2.0f * c0b;
            uint2 w;
            w.x = packbf(c1a, c1b);
            w.y = packbf(c0a, c0b);
            dst[k * 256] = w;
        }
    } else {
        __shared__ float sh[MM];
        if (t == 0) g_ctr = NCTA;
        float w = W[t];
        sh[t] = w;
        __syncthreads();
        for (int s = MM / 2; s > 0; s >>= 1) {
            if (t < s) sh[t] = fmaxf(sh[t], sh[t + s]);
            __syncthreads();
        }
        float mx = sh[0];
        __syncthreads();
        sh[t] = expf(w - mx);
        __syncthreads();
        for (int s = MM / 2; s > 0; s >>= 1) {
            if (t < s) sh[t] += sh[t + s];
            __syncthreads();
        }
        g_logw[t] = w - (mx + logf(sh[0]));
    }
}

// ---------------------------------------------------------------------------
// Main: 148 persistent CTAs x 512 threads; dynamic tiles 32b x 64m x 1024d.
// Threads = 16(tx,m) x 8(ty,b) x 4(tz,d-quarter); thread tile 4b x 4m over a
// 32-d quarter of each 128-d chunk. 3-slot cp.async ring streams chunks
// across tile boundaries, ONE __syncthreads per chunk. bf16 HFMA2/HMUL2
// inner; __log2f merge per chunk (32 d / accumulator). Epilogue combines the
// 4 tz-quarters via a dedicated smem region (no overlap with ring slots).
// ---------------------------------------------------------------------------
__global__ void __launch_bounds__(512, 1) main_kernel() {
    extern __shared__ uint4 sm[];
    uint4* xs = sm;                          // 3 x XSTG
    uint4* cs = sm + 3 * XSTG;               // 3 x CSTG
    float* epi = (float*)(sm + 3 * (XSTG + CSTG));   // 3 x 128 x 17 floats
    __shared__ int sh_t;

    const int t  = threadIdx.x;
    const int tx = t & 15;
    const int ty = (t >> 4) & 7;
    const int tz = t >> 7;

    // fetch mappings
    const int xrow = t >> 4, xq = t & 15;    // x: 32 rows x 16 uint4
    const int crow = t >> 3, cu = t & 7;     // c: 64 rows, 4 uint4 per thread
    const uint32_t xd = (uint32_t)__cvta_generic_to_shared(&xs[xrow * 16 + xq]);
    const uint32_t cd = (uint32_t)__cvta_generic_to_shared(&cs[crow * 33 + cu]);

    auto issue = [&](int tile, int ck, int slot) {
        if (tile < NT2) {
            int bT = tile >> 2, mT = tile & 3;
            const uint32_t* xp = g_xb + (size_t)(bT * 32 + xrow) * (DD / 2)
                                 + ck * 64 + xq * 4;
            cp16(xd + slot * XSTG * 16, xp);
            const uint32_t* cp = g_cb + (size_t)(mT * 64 + crow) * DD
                                 + ck * 128 + cu * 4;
            uint32_t cb = cd + slot * CSTG * 16;
#pragma unroll
            for (int k = 0; k < 4; k++)
                cp16(cb + k * 128, cp + k * 32);
        }
        asm volatile("cp.async.commit_group;");
    };

    auto grab = [&]() -> int {
        __syncthreads();
        if (t == 0) sh_t = atomicAdd(&g_ctr, 1);
        __syncthreads();
        return sh_t;
    };

    int cur = blockIdx.x;                    // < NT2
    issue(cur, 0, 0);
    issue(cur, 1, 1);
    int nxt = grab();
    int islot = 2, cslot = 0;

    const uint32_t ONE2 = 0x3F803F80u;       // bf16x2 {1.0, 1.0}

    while (cur < NT2) {
        float acc[4][4];
#pragma unroll
        for (int i = 0; i < 4; i++)
#pragma unroll
            for (int jm = 0; jm < 4; jm++) acc[i][jm] = 0.0f;

        for (int ck = 0; ck < NCH; ck++) {
            asm volatile("cp.async.wait_group 1;");
            __syncthreads();
            {
                int fck = ck + 2, ft = cur;
                if (fck >= NCH) { fck -= NCH; ft = nxt; }
                issue(ft, fck, islot);
                islot = (islot == 2) ? 0 : islot + 1;
            }
            const uint4* xb = xs + cslot * XSTG + ty * 16 + tz * 4;
            const uint4* cb = cs + cslot * CSTG + tx * 33 + tz * 8;
            cslot = (cslot == 2) ? 0 : cslot + 1;

            __nv_bfloat162 prod[4][4];
#pragma unroll
            for (int i = 0; i < 4; i++)
#pragma unroll
                for (int jm = 0; jm < 4; jm++) prod[i][jm] = asbf2(ONE2);

#pragma unroll
            for (int jq = 0; jq < 4; jq++) {          // 8 d per jq (per tz quarter)
                uint4 xv[4];
#pragma unroll
                for (int i = 0; i < 4; i++) xv[i] = xb[i * 8 * 16 + jq];
#pragma unroll
                for (int jm = 0; jm < 4; jm++) {
                    uint4 c0 = cb[jm * 16 * 33 + jq * 2];
                    uint4 c1 = cb[jm * 16 * 33 + jq * 2 + 1];
#pragma unroll
                    for (int i = 0; i < 4; i++) {
                        __nv_bfloat162 l0 = __hfma2(asbf2(c0.x), asbf2(xv[i].x), asbf2(c0.y));
                        __nv_bfloat162 l1 = __hfma2(asbf2(c0.z), asbf2(xv[i].y), asbf2(c0.w));
                        __nv_bfloat162 l2 = __hfma2(asbf2(c1.x), asbf2(xv[i].z), asbf2(c1.y));
                        __nv_bfloat162 l3 = __hfma2(asbf2(c1.z), asbf2(xv[i].w), asbf2(c1.w));
                        prod[i][jm] = __hmul2(prod[i][jm],
                                              __hmul2(__hmul2(l0, l1), __hmul2(l2, l3)));
                    }
                }
            }
            // merge: 32 d per accumulator this chunk (scaled x2: safe)
#pragma unroll
            for (int i = 0; i < 4; i++)
#pragma unroll
                for (int jm = 0; jm < 4; jm++) {
                    uint32_t u = asu32(prod[i][jm]);
                    float hi = __uint_as_float(u & 0xFFFF0000u);
                    float lo = __uint_as_float(u << 16);
                    acc[i][jm] += __log2f(hi * lo);
                }
        }

        // ---- epilogue: combine tz quarters (dedicated smem region) ----
        {
            const int id = t & 127;                   // (tx,ty)
            if (tz > 0) {
#pragma unroll
                for (int i = 0; i < 4; i++)
#pragma unroll
                    for (int jm = 0; jm < 4; jm++)
                        epi[(tz - 1) * 2176 + id * 17 + i * 4 + jm] = acc[i][jm];
            }
            __syncthreads();
            if (tz == 0) {
                int bT = cur >> 2, mT = cur & 3;
#pragma unroll
                for (int i = 0; i < 4; i++)
#pragma unroll
                    for (int jm = 0; jm < 4; jm++) {
                        float a = acc[i][jm]
                                + epi[0 * 2176 + id * 17 + i * 4 + jm]
                                + epi[1 * 2176 + id * 17 + i * 4 + jm]
                                + epi[2 * 2176 + id * 17 + i * 4 + jm];
                        g_comp[(size_t)(bT * 32 + ty + 8 * i) * MM
                               + (mT * 64 + tx + 16 * jm)] = a;
                    }
            }
            __syncthreads();   // epi reusable next tile
        }

        cur = nxt;
        nxt = grab();
    }
    asm volatile("cp.async.wait_group 0;");
}

// ---------------------------------------------------------------------------
// Reduce: one warp per batch. comp_ll = (acc2 - 1024)*ln2 + logw, then
// logsumexp over 256 components.
// ---------------------------------------------------------------------------
__global__ void reduce_kernel(float* __restrict__ out) {
    const float LN2 = 0.69314718055994531f;
    int w = (blockIdx.x << 4) + (threadIdx.x >> 5);
    int lane = threadIdx.x & 31;
    const float4* cp4 = reinterpret_cast<const float4*>(g_comp + (size_t)w * MM) + lane * 2;
    const float4* lw4 = reinterpret_cast<const float4*>(g_logw) + lane * 2;
    float v[8];
    float mx = -1e30f;
#pragma unroll
    for (int k = 0; k < 2; k++) {
        float4 c = cp4[k];
        float4 l = lw4[k];
        v[k*4+0] = (c.x - 1024.0f) * LN2 + l.x;
        v[k*4+1] = (c.y - 1024.0f) * LN2 + l.y;
        v[k*4+2] = (c.z - 1024.0f) * LN2 + l.z;
        v[k*4+3] = (c.w - 1024.0f) * LN2 + l.w;
#pragma unroll
        for (int j = 0; j < 4; j++) mx = fmaxf(mx, v[k*4+j]);
    }
#pragma unroll
    for (int o = 16; o > 0; o >>= 1) mx = fmaxf(mx, __shfl_xor_sync(0xFFFFFFFFu, mx, o));
    float s = 0.0f;
#pragma unroll
    for (int k = 0; k < 8; k++) s += __expf(v[k] - mx);
#pragma unroll
    for (int o = 16; o > 0; o >>= 1) s += __shfl_xor_sync(0xFFFFFFFFu, s, o);
    if (lane == 0) out[w] = mx + __logf(s);
}

extern "C" void kernel_launch(void* const* d_in, const int* in_sizes, int n_in,
                              void* d_out, int out_size) {
    const float* x = nullptr;
    const float* W = nullptr;
    const float* P = nullptr;
    for (int i = 0; i < n_in; i++) {
        if      (in_sizes[i] == BB * DD) x = (const float*)d_in[i];
        else if (in_sizes[i] == MM)      W = (const float*)d_in[i];
        else if (in_sizes[i] == MM * DD) P = (const float*)d_in[i];
    }

    prep_kernel<<<321, 256>>>(x, P, W);

    const int SMEM = (3 * (XSTG + CSTG) + 1632) * 16;   // 125,952 + 26,112 = 152,064
    cudaFuncSetAttribute(main_kernel, cudaFuncAttributeMaxDynamicSharedMemorySize, SMEM);
    main_kernel<<<NCTA, 512, SMEM>>>();

    reduce_kernel<<<BB / 16, 512>>>((float*)d_out);
}

// round 14
// speedup vs baseline: 1.0752x; 1.0752x over previous
#include <cuda_runtime.h>
#include <cuda_bf16.h>
#include <cstdint>
#include <cstring>

#define DD 1024
#define MM 256
#define BB 2048
#define NTILE 1024     // 32b x 32m x 512d tiles: 64 bT x 8 (mT,dH)
#define NCTA 148
#define XSTG 512       // uint4 per x stage (32 rows x 16)
#define CSTG 1056      // uint4 per c stage (32 rows x 33, odd stride)

// Device scratch (no allocations allowed)
__device__ __align__(16) uint32_t g_cb[MM * DD];          // per d-pair: {c1 bf16x2, c0 bf16x2}
__device__ __align__(16) uint32_t g_xb[BB * (DD / 2)];    // x as bf16x2 pairs
__device__ __align__(16) float g_logw[MM];
__device__ __align__(16) float g_part[2][BB * MM];        // per d-half partial log2 sums

__device__ __forceinline__ __nv_bfloat162 asbf2(uint32_t u) {
    __nv_bfloat162 r; memcpy(&r, &u, 4); return r;
}
__device__ __forceinline__ uint32_t asu32(__nv_bfloat162 b) {
    uint32_t u; memcpy(&u, &b, 4); return u;
}
__device__ __forceinline__ void cp16(uint32_t dst, const void* src) {
    asm volatile("cp.async.ca.shared.global [%0], [%1], 16;" :: "r"(dst), "l"(src));
}
__device__ __forceinline__ uint32_t packbf(float a, float b) {
    return asu32(__floats2bfloat162_rn(a, b));
}

// ---------------------------------------------------------------------------
// Fused prep (R8): blocks [0,256) x->bf16 (MLP8 loads, STG.128 stores);
// [256,320) P->coefs (MLP8); block 320: logw.
// ---------------------------------------------------------------------------
__global__ void prep_kernel(const float* __restrict__ x,
                            const float* __restrict__ P,
                            const float* __restrict__ W) {
    int bk = blockIdx.x, t = threadIdx.x;
    if (bk < 256) {
        const float4* src = reinterpret_cast<const float4*>(x) + bk * 2048;
        uint4* dst = reinterpret_cast<uint4*>(g_xb) + bk * 1024;
        float4 v[4][2];
#pragma unroll
        for (int k = 0; k < 4; k++) {
            v[k][0] = src[k * 512 + t * 2];
            v[k][1] = src[k * 512 + t * 2 + 1];
        }
#pragma unroll
        for (int k = 0; k < 4; k++) {
            uint4 w;
            w.x = packbf(v[k][0].x, v[k][0].y);
            w.y = packbf(v[k][0].z, v[k][0].w);
            w.z = packbf(v[k][1].x, v[k][1].y);
            w.w = packbf(v[k][1].z, v[k][1].w);
            dst[k * 256 + t] = w;
        }
    } else if (bk < 320) {
        int b2 = bk - 256;
        const float2* src = reinterpret_cast<const float2*>(P) + b2 * 2048 + t;
        uint2* dst = reinterpret_cast<uint2*>(g_cb) + b2 * 2048 + t;
        float2 v[8];
#pragma unroll
        for (int k = 0; k < 8; k++) v[k] = src[k * 256];
#pragma unroll
        for (int k = 0; k < 8; k++) {
            float c0a = 2.0f / (1.0f + __expf(v[k].x));   // 2*(1-p)
            float c0b = 2.0f / (1.0f + __expf(v[k].y));
            float c1a = 2.0f - 2.0f * c0a;                // 2*(2p-1)
            float c1b = 2.0f - 2.0f * c0b;
            uint2 w;
            w.x = packbf(c1a, c1b);
            w.y = packbf(c0a, c0b);
            dst[k * 256] = w;
        }
    } else {
        __shared__ float sh[MM];
        float w = W[t];
        sh[t] = w;
        __syncthreads();
        for (int s = MM / 2; s > 0; s >>= 1) {
            if (t < s) sh[t] = fmaxf(sh[t], sh[t + s]);
            __syncthreads();
        }
        float mx = sh[0];
        __syncthreads();
        sh[t] = expf(w - mx);
        __syncthreads();
        for (int s = MM / 2; s > 0; s >>= 1) {
            if (t < s) sh[t] += sh[t + s];
            __syncthreads();
        }
        g_logw[t] = w - (mx + logf(sh[0]));
    }
}

// ---------------------------------------------------------------------------
// Main: 148 persistent CTAs x 256 threads (2 CTAs/SM). CTA k statically owns
// tiles [k*1024/148, (k+1)*1024/148) of 1024 fine tiles (32b x 32m x 512d),
// linearized (mT*2+dH)*64 + bT. Continuous chunk stream (128 d/chunk,
// 4 chunks/tile) through a 3-slot cp.async ring: ONE __syncthreads per chunk,
// no drain at tile boundaries. Threads = 8(tx,m) x 8(ty,b) x 4(tz,d-quarter),
// thread tile 4b x 4m. bf16 HFMA2/HMUL2 inner; __log2f merge every 2 chunks.
// Epilogue every 4 chunks combines tz quarters -> g_part[dH].
// ---------------------------------------------------------------------------
__global__ void __launch_bounds__(256, 2) main_kernel() {
    extern __shared__ uint4 sm[];
    uint4* xs = sm;                                   // 3 x XSTG
    uint4* cs = sm + 3 * XSTG;                        // 3 x CSTG
    float* epi = (float*)(sm + 3 * (XSTG + CSTG));    // 3 x 64 x 17 floats

    const int t  = threadIdx.x;
    const int tx = t & 7;
    const int ty = (t >> 3) & 7;
    const int tz = t >> 6;

    const int s4 = (int)(((long)blockIdx.x * NTILE) / NCTA) * 4;
    const int e4 = (int)(((long)(blockIdx.x + 1) * NTILE) / NCTA) * 4;

    // fetch mappings: 32 rows, 8 quad-slots per thread set
    const int fr = t >> 3, fq = t & 7;
    const uint32_t xd = (uint32_t)__cvta_generic_to_shared(&xs[fr * 16 + fq]);
    const uint32_t cd = (uint32_t)__cvta_generic_to_shared(&cs[fr * 33 + fq]);

    auto issue = [&](int gck, int slot) {
        if (gck < e4) {
            int tile = gck >> 2, ck = gck & 3;
            int bT = tile & 63, md = tile >> 6;
            int dH = md & 1, mT = md >> 1;
            const uint32_t* xp = g_xb + ((size_t)(bT * 32 + fr) << 9)
                                 + (dH << 8) + (ck << 6) + fq * 4;
            uint32_t xb_ = xd + slot * XSTG * 16;
            cp16(xb_,          xp);
            cp16(xb_ + 8 * 16, xp + 32);
            const uint32_t* cp = g_cb + ((size_t)(mT * 32 + fr) << 10)
                                 + (dH << 9) + (ck << 7) + fq * 4;
            uint32_t cb_ = cd + slot * CSTG * 16;
#pragma unroll
            for (int k = 0; k < 4; k++)
                cp16(cb_ + k * 8 * 16, cp + k * 32);
        }
        asm volatile("cp.async.commit_group;");
    };

    issue(s4,     0);
    issue(s4 + 1, 1);

    const uint32_t ONE2 = 0x3F803F80u;   // bf16x2 {1.0, 1.0}
    __nv_bfloat162 prod[4][4];
    float acc[4][4];
#pragma unroll
    for (int i = 0; i < 4; i++)
#pragma unroll
        for (int jm = 0; jm < 4; jm++) { prod[i][jm] = asbf2(ONE2); acc[i][jm] = 0.0f; }

    for (int gck = s4; gck < e4; gck++) {
        asm volatile("cp.async.wait_group 1;");
        __syncthreads();
        const int r = gck - s4;
        issue(gck + 2, (r + 2) % 3);

        const uint4* xb = xs + (r % 3) * XSTG + tz * 4;
        const uint4* cb = cs + (r % 3) * CSTG + tx * 33 + tz * 8;

#pragma unroll
        for (int jq = 0; jq < 4; jq++) {          // 8 d per jq (per tz quarter)
            uint4 xv[4];
#pragma unroll
            for (int i = 0; i < 4; i++) xv[i] = xb[(i * 8 + ty) * 16 + jq];
#pragma unroll
            for (int jm = 0; jm < 4; jm++) {
                uint4 c0 = cb[jm * 8 * 33 + jq * 2];
                uint4 c1 = cb[jm * 8 * 33 + jq * 2 + 1];
#pragma unroll
                for (int i = 0; i < 4; i++) {
                    __nv_bfloat162 l0 = __hfma2(asbf2(c0.x), asbf2(xv[i].x), asbf2(c0.y));
                    __nv_bfloat162 l1 = __hfma2(asbf2(c0.z), asbf2(xv[i].y), asbf2(c0.w));
                    __nv_bfloat162 l2 = __hfma2(asbf2(c1.x), asbf2(xv[i].z), asbf2(c1.y));
                    __nv_bfloat162 l3 = __hfma2(asbf2(c1.z), asbf2(xv[i].w), asbf2(c1.w));
                    prod[i][jm] = __hmul2(prod[i][jm],
                                          __hmul2(__hmul2(l0, l1), __hmul2(l2, l3)));
                }
            }
        }
        if (gck & 1) {   // merge every 64 d (scaled x2: safe fp32 range)
#pragma unroll
            for (int i = 0; i < 4; i++)
#pragma unroll
                for (int jm = 0; jm < 4; jm++) {
                    uint32_t u = asu32(prod[i][jm]);
                    float hi = __uint_as_float(u & 0xFFFF0000u);
                    float lo = __uint_as_float(u << 16);
                    acc[i][jm] += __log2f(hi * lo);
                    prod[i][jm] = asbf2(ONE2);
                }
        }
        if ((gck & 3) == 3) {   // ---- tile epilogue ----
            int tile = gck >> 2;
            int bT = tile & 63, md = tile >> 6;
            int dH = md & 1, mT = md >> 1;
            const int id = t & 63;
            if (tz > 0) {
#pragma unroll
                for (int i = 0; i < 4; i++)
#pragma unroll
                    for (int jm = 0; jm < 4; jm++)
                        epi[(tz - 1) * 1088 + id * 17 + i * 4 + jm] = acc[i][jm];
            }
            __syncthreads();
            if (tz == 0) {
                float* base = g_part[dH];
#pragma unroll
                for (int i = 0; i < 4; i++)
#pragma unroll
                    for (int jm = 0; jm < 4; jm++) {
                        float a = acc[i][jm]
                                + epi[0 * 1088 + id * 17 + i * 4 + jm]
                                + epi[1 * 1088 + id * 17 + i * 4 + jm]
                                + epi[2 * 1088 + id * 17 + i * 4 + jm];
                        base[(size_t)(bT * 32 + ty + 8 * i) * MM
                             + (mT * 32 + tx + 8 * jm)] = a;
                    }
            }
#pragma unroll
            for (int i = 0; i < 4; i++)
#pragma unroll
                for (int jm = 0; jm < 4; jm++) acc[i][jm] = 0.0f;
        }
    }
    asm volatile("cp.async.wait_group 0;");
}

// ---------------------------------------------------------------------------
// Reduce: one warp per batch. comp = (p0+p1-1024)*ln2 + logw, then
// logsumexp over 256 components.
// ---------------------------------------------------------------------------
__global__ void reduce_kernel(float* __restrict__ out) {
    const float LN2 = 0.69314718055994531f;
    int w = (blockIdx.x << 4) + (threadIdx.x >> 5);
    int lane = threadIdx.x & 31;
    const float4* p0 = reinterpret_cast<const float4*>(g_part[0] + (size_t)w * MM) + lane * 2;
    const float4* p1 = reinterpret_cast<const float4*>(g_part[1] + (size_t)w * MM) + lane * 2;
    const float4* lw = reinterpret_cast<const float4*>(g_logw) + lane * 2;
    float v[8];
    float mx = -1e30f;
#pragma unroll
    for (int k = 0; k < 2; k++) {
        float4 a = p0[k], b = p1[k], l = lw[k];
        v[k*4+0] = (a.x + b.x - 1024.0f) * LN2 + l.x;
        v[k*4+1] = (a.y + b.y - 1024.0f) * LN2 + l.y;
        v[k*4+2] = (a.z + b.z - 1024.0f) * LN2 + l.z;
        v[k*4+3] = (a.w + b.w - 1024.0f) * LN2 + l.w;
#pragma unroll
        for (int j = 0; j < 4; j++) mx = fmaxf(mx, v[k*4+j]);
    }
#pragma unroll
    for (int o = 16; o > 0; o >>= 1) mx = fmaxf(mx, __shfl_xor_sync(0xFFFFFFFFu, mx, o));
    float s = 0.0f;
#pragma unroll
    for (int k = 0; k < 8; k++) s += __expf(v[k] - mx);
#pragma unroll
    for (int o = 16; o > 0; o >>= 1) s += __shfl_xor_sync(0xFFFFFFFFu, s, o);
    if (lane == 0) out[w] = mx + __logf(s);
}

extern "C" void kernel_launch(void* const* d_in, const int* in_sizes, int n_in,
                              void* d_out, int out_size) {
    const float* x = nullptr;
    const float* W = nullptr;
    const float* P = nullptr;
    for (int i = 0; i < n_in; i++) {
        if      (in_sizes[i] == BB * DD) x = (const float*)d_in[i];
        else if (in_sizes[i] == MM)      W = (const float*)d_in[i];
        else if (in_sizes[i] == MM * DD) P = (const float*)d_in[i];
    }

    prep_kernel<<<321, 256>>>(x, P, W);

    const int SMEM = 3 * (XSTG + CSTG) * 16 + 3264 * 4;   // 75,264 + 13,056 = 88,320
    cudaFuncSetAttribute(main_kernel, cudaFuncAttributeMaxDynamicSharedMemorySize, SMEM);
    main_kernel<<<NCTA, 256, SMEM>>>();

    reduce_kernel<<<BB / 16, 512>>>((float*)d_out);
}

// round 15
// speedup vs baseline: 1.1244x; 1.0458x over previous
#include <cuda_runtime.h>
#include <cuda_bf16.h>
#include <cstdint>
#include <cstring>

#define DD 1024
#define MM 256
#define BB 2048
#define NCH 8          // 8 chunks x 128 d
#define XSTG 1024      // uint4 per x stage (64 rows x 16)
#define CSTG 2112      // uint4 per c stage (64 rows x 33, odd stride)

// Device scratch (no allocations allowed)
__device__ __align__(16) uint32_t g_cb[MM * DD];          // per d-pair: {c1 bf16x2, c0 bf16x2}
__device__ __align__(16) uint32_t g_xb[BB * (DD / 2)];    // x as bf16x2 pairs
__device__ __align__(16) float g_logw[MM];
__device__ __align__(16) float g_comp[BB * MM];           // sum over d of log2(2*lik)

__device__ __forceinline__ __nv_bfloat162 asbf2(uint32_t u) {
    __nv_bfloat162 r; memcpy(&r, &u, 4); return r;
}
__device__ __forceinline__ uint32_t asu32(__nv_bfloat162 b) {
    uint32_t u; memcpy(&u, &b, 4); return u;
}
__device__ __forceinline__ void cp16(uint32_t dst, const void* src) {
    asm volatile("cp.async.ca.shared.global [%0], [%1], 16;" :: "r"(dst), "l"(src));
}
__device__ __forceinline__ uint32_t packbf(float a, float b) {
    return asu32(__floats2bfloat162_rn(a, b));
}

// ---------------------------------------------------------------------------
// Fused prep: blocks [0,256) x->bf16; [256,320) P->coefs; block 320: logw.
// __launch_bounds__(256, 1) lifts the register cap so the 8 batched LDG.128
// stay in flight (true MLP-8) instead of ptxas serializing at 34 regs.
// ---------------------------------------------------------------------------
__global__ void __launch_bounds__(256, 1) prep_kernel(const float* __restrict__ x,
                                                      const float* __restrict__ P,
                                                      const float* __restrict__ W) {
    int bk = blockIdx.x, t = threadIdx.x;
    if (bk < 256) {
        const float4* src = reinterpret_cast<const float4*>(x) + bk * 2048;
        uint4* dst = reinterpret_cast<uint4*>(g_xb) + bk * 1024;
        float4 v[8];
#pragma unroll
        for (int k = 0; k < 4; k++) {
            v[2 * k]     = src[k * 512 + t * 2];
            v[2 * k + 1] = src[k * 512 + t * 2 + 1];
        }
        uint4 w[4];
#pragma unroll
        for (int k = 0; k < 4; k++) {
            w[k].x = packbf(v[2 * k].x,     v[2 * k].y);
            w[k].y = packbf(v[2 * k].z,     v[2 * k].w);
            w[k].z = packbf(v[2 * k + 1].x, v[2 * k + 1].y);
            w[k].w = packbf(v[2 * k + 1].z, v[2 * k + 1].w);
        }
#pragma unroll
        for (int k = 0; k < 4; k++) dst[k * 256 + t] = w[k];
    } else if (bk < 320) {
        int b2 = bk - 256;
        const float2* src = reinterpret_cast<const float2*>(P) + b2 * 2048 + t;
        uint2* dst = reinterpret_cast<uint2*>(g_cb) + b2 * 2048 + t;
        float2 v[8];
#pragma unroll
        for (int k = 0; k < 8; k++) v[k] = src[k * 256];
        uint2 w[8];
#pragma unroll
        for (int k = 0; k < 8; k++) {
            float c0a = 2.0f / (1.0f + __expf(v[k].x));   // 2*(1-p)
            float c0b = 2.0f / (1.0f + __expf(v[k].y));
            float c1a = 2.0f - 2.0f * c0a;                // 2*(2p-1)
            float c1b = 2.0f - 2.0f * c0b;
            w[k].x = packbf(c1a, c1b);
            w[k].y = packbf(c0a, c0b);
        }
#pragma unroll
        for (int k = 0; k < 8; k++) dst[k * 256] = w[k];
    } else {
        __shared__ float sh[MM];
        float w = W[t];
        sh[t] = w;
        __syncthreads();
        for (int s = MM / 2; s > 0; s >>= 1) {
            if (t < s) sh[t] = fmaxf(sh[t], sh[t + s]);
            __syncthreads();
        }
        float mx = sh[0];
        __syncthreads();
        sh[t] = expf(w - mx);
        __syncthreads();
        for (int s = MM / 2; s > 0; s >>= 1) {
            if (t < s) sh[t] += sh[t + s];
            __syncthreads();
        }
        g_logw[t] = w - (mx + logf(sh[0]));
    }
}

// ---------------------------------------------------------------------------
// Main (R8, frozen): block 64b x 64m, 512 threads = 16(tx,m) x 16(ty,b) x
// 2(tz,d-split), thread tile 4b x 4m over half of each 128-d chunk. 3-stage
// cp.async ring, ONE __syncthreads per chunk. bf16 HFMA2/HMUL2 inner;
// __log2f merge per chunk (64 d per accumulator).
// ---------------------------------------------------------------------------
__global__ void __launch_bounds__(512, 1) main_kernel() {
    extern __shared__ uint4 sm[];
    uint4* xs = sm;                // 3 stages x XSTG
    uint4* cs = sm + 3 * XSTG;     // 3 stages x CSTG

    const int t  = threadIdx.x;
    const int tx = t & 15;
    const int ty = (t >> 4) & 15;
    const int tz = t >> 8;
    const int bBase = blockIdx.x * 64;
    const int mBase = blockIdx.y * 64;

    const int xr = t >> 3, xq = t & 7;
    const uint32_t* xsrc = g_xb + (size_t)(bBase + xr) * (DD / 2) + xq * 4;
    const uint32_t* csrc = g_cb + (size_t)(mBase + xr) * DD + xq * 4;
    const uint32_t xd = (uint32_t)__cvta_generic_to_shared(&xs[xr * 16 + xq]);
    const uint32_t cd = (uint32_t)__cvta_generic_to_shared(&cs[xr * 33 + xq]);

    auto issue = [&](int ck, int slot) {
        const uint32_t* xp = xsrc + ck * 64;
        uint32_t xb = xd + slot * XSTG * 16;
        cp16(xb,          xp);
        cp16(xb + 8 * 16, xp + 32);
        const uint32_t* cp = csrc + ck * 128;
        uint32_t cb = cd + slot * CSTG * 16;
        cp16(cb,           cp);
        cp16(cb + 8 * 16,  cp + 32);
        cp16(cb + 16 * 16, cp + 64);
        cp16(cb + 24 * 16, cp + 96);
        asm volatile("cp.async.commit_group;");
    };

    issue(0, 0);
    issue(1, 1);

    const uint32_t ONE2 = 0x3F803F80u;   // bf16x2 {1.0, 1.0}
    float acc[4][4];
#pragma unroll
    for (int i = 0; i < 4; i++)
#pragma unroll
        for (int jm = 0; jm < 4; jm++) acc[i][jm] = 0.0f;

    for (int ck = 0; ck < NCH; ck++) {
        asm volatile("cp.async.wait_group 1;");
        __syncthreads();
        if (ck + 2 < NCH) issue(ck + 2, (ck + 2) % 3);
        else asm volatile("cp.async.commit_group;");

        const int slot = ck % 3;
        const uint4* xb = xs + slot * XSTG + ty * 16 + tz * 8;
        const uint4* cb = cs + slot * CSTG + tx * 33 + tz * 16;

        __nv_bfloat162 prod[4][4];
#pragma unroll
        for (int i = 0; i < 4; i++)
#pragma unroll
            for (int jm = 0; jm < 4; jm++) prod[i][jm] = asbf2(ONE2);

#pragma unroll
        for (int jq = 0; jq < 8; jq++) {          // 8 d per jq (per tz half)
            uint4 xv[4];
#pragma unroll
            for (int i = 0; i < 4; i++) xv[i] = xb[i * 16 * 16 + jq];
#pragma unroll
            for (int jm = 0; jm < 4; jm++) {
                uint4 c0 = cb[jm * 16 * 33 + jq * 2];
                uint4 c1 = cb[jm * 16 * 33 + jq * 2 + 1];
#pragma unroll
                for (int i = 0; i < 4; i++) {
                    __nv_bfloat162 l0 = __hfma2(asbf2(c0.x), asbf2(xv[i].x), asbf2(c0.y));
                    __nv_bfloat162 l1 = __hfma2(asbf2(c0.z), asbf2(xv[i].y), asbf2(c0.w));
                    __nv_bfloat162 l2 = __hfma2(asbf2(c1.x), asbf2(xv[i].z), asbf2(c1.y));
                    __nv_bfloat162 l3 = __hfma2(asbf2(c1.z), asbf2(xv[i].w), asbf2(c1.w));
                    prod[i][jm] = __hmul2(prod[i][jm],
                                          __hmul2(__hmul2(l0, l1), __hmul2(l2, l3)));
                }
            }
        }
        // merge: 64 d per accumulator (scaled x2: safe fp32 range)
#pragma unroll
        for (int i = 0; i < 4; i++)
#pragma unroll
            for (int jm = 0; jm < 4; jm++) {
                uint32_t u = asu32(prod[i][jm]);
                float hi = __uint_as_float(u & 0xFFFF0000u);
                float lo = __uint_as_float(u << 16);
                acc[i][jm] += __log2f(hi * lo);
            }
    }

    asm volatile("cp.async.wait_group 0;");
    __syncthreads();
    // combine tz halves through smem (stride 17 floats: no bank conflicts)
    float* sh = (float*)sm;
    const int tid256 = t & 255;
    if (tz == 1) {
#pragma unroll
        for (int i = 0; i < 4; i++)
#pragma unroll
            for (int jm = 0; jm < 4; jm++)
                sh[tid256 * 17 + i * 4 + jm] = acc[i][jm];
    }
    __syncthreads();
    if (tz == 0) {
#pragma unroll
        for (int i = 0; i < 4; i++)
#pragma unroll
            for (int jm = 0; jm < 4; jm++) {
                float a = acc[i][jm] + sh[tid256 * 17 + i * 4 + jm];
                g_comp[(size_t)(bBase + ty + 16 * i) * MM + (mBase + tx + 16 * jm)] = a;
            }
    }
}

// ---------------------------------------------------------------------------
// Reduce: one warp per batch. comp_ll = (acc2 - 1024)*ln2 + logw, then
// logsumexp over 256 components.
// ---------------------------------------------------------------------------
__global__ void reduce_kernel(float* __restrict__ out) {
    const float LN2 = 0.69314718055994531f;
    int w = (blockIdx.x << 4) + (threadIdx.x >> 5);
    int lane = threadIdx.x & 31;
    const float4* cp4 = reinterpret_cast<const float4*>(g_comp + (size_t)w * MM) + lane * 2;
    const float4* lw4 = reinterpret_cast<const float4*>(g_logw) + lane * 2;
    float v[8];
    float mx = -1e30f;
#pragma unroll
    for (int k = 0; k < 2; k++) {
        float4 c = cp4[k];
        float4 l = lw4[k];
        v[k*4+0] = (c.x - 1024.0f) * LN2 + l.x;
        v[k*4+1] = (c.y - 1024.0f) * LN2 + l.y;
        v[k*4+2] = (c.z - 1024.0f) * LN2 + l.z;
        v[k*4+3] = (c.w - 1024.0f) * LN2 + l.w;
#pragma unroll
        for (int j = 0; j < 4; j++) mx = fmaxf(mx, v[k*4+j]);
    }
#pragma unroll
    for (int o = 16; o > 0; o >>= 1) mx = fmaxf(mx, __shfl_xor_sync(0xFFFFFFFFu, mx, o));
    float s = 0.0f;
#pragma unroll
    for (int k = 0; k < 8; k++) s += __expf(v[k] - mx);
#pragma unroll
    for (int o = 16; o > 0; o >>= 1) s += __shfl_xor_sync(0xFFFFFFFFu, s, o);
    if (lane == 0) out[w] = mx + __logf(s);
}

extern "C" void kernel_launch(void* const* d_in, const int* in_sizes, int n_in,
                              void* d_out, int out_size) {
    const float* x = nullptr;
    const float* W = nullptr;
    const float* P = nullptr;
    for (int i = 0; i < n_in; i++) {
        if      (in_sizes[i] == BB * DD) x = (const float*)d_in[i];
        else if (in_sizes[i] == MM)      W = (const float*)d_in[i];
        else if (in_sizes[i] == MM * DD) P = (const float*)d_in[i];
    }

    prep_kernel<<<321, 256>>>(x, P, W);

    const int SMEM = 3 * (XSTG + CSTG) * 16;   // 150,528 bytes
    cudaFuncSetAttribute(main_kernel, cudaFuncAttributeMaxDynamicSharedMemorySize, SMEM);
    dim3 grid(BB / 64, MM / 64);
    main_kernel<<<grid, 512, SMEM>>>();

    reduce_kernel<<<BB / 16, 512>>>((float*)d_out);
}